// round 6
// baseline (speedup 1.0000x reference)
#include <cuda_runtime.h>
#include <cuda_bf16.h>
#include <cstdint>

#define NLAYERS 15

// ---- arch-feature gate: tcgen05 only exists on sm_103a/'f' feature targets ----
#if defined(__CUDA_ARCH__)
#  if defined(__CUDA_ARCH_FEAT_SM103_ALL) || defined(__CUDA_ARCH_FEAT_SM100_ALL) || defined(__CUDA_ARCH_FAMILY_SPECIFIC__)
#    define USE_TC05 1
#  else
#    define USE_TC05 0
#  endif
#else
#  define USE_TC05 0
#endif

// ---------------- common helpers ----------------
static __device__ __forceinline__ uint32_t pack2(float e0, float e1) {
    uint32_t r;
    asm("cvt.rn.bf16x2.f32 %0, %1, %2;" : "=r"(r) : "f"(e1), "f"(e0));
    return r;
}
static __device__ __forceinline__ float bf16_round(float a) {
    return __bfloat162float(__float2bfloat16_rn(a));
}

// One global weight image; format depends on which branch compiled (both are 15*4096 uint4).
__device__ uint4 g_W[NLAYERS * 4096];

#if USE_TC05
__device__ __forceinline__ uint32_t elect_one_pred() {
    uint32_t pred;
    asm volatile("{\n\t.reg .pred p;\n\telect.sync _|p, 0xFFFFFFFF;\n\tselp.b32 %0, 1, 0, p;\n\t}"
                 : "=r"(pred));
    return pred;
}
#endif
__device__ __forceinline__ uint32_t smem_to_u32(const void* p) {
    uint32_t a;
    asm("{ .reg .u64 t; cvta.to.shared.u64 t, %1; cvt.u32.u64 %0, t; }" : "=r"(a) : "l"(p));
    return a;
}

#if USE_TC05
#define TCGEN05_ALLOC(smem_result_addr, nCols) \
    asm volatile("tcgen05.alloc.cta_group::1.sync.aligned.shared::cta.b32 [%0], %1;" \
                 :: "r"((uint32_t)(smem_result_addr)), "r"((uint32_t)(nCols)) : "memory")
#define TCGEN05_DEALLOC(tmem_addr, nCols) \
    asm volatile("tcgen05.dealloc.cta_group::1.sync.aligned.b32 %0, %1;" :: "r"(tmem_addr), "r"((uint32_t)(nCols)))
#define TCGEN05_RELINQUISH() \
    asm volatile("tcgen05.relinquish_alloc_permit.cta_group::1.sync.aligned;")
#define TCGEN05_WAIT_LD() asm volatile("tcgen05.wait::ld.sync.aligned;" ::: "memory")
#define TCGEN05_WAIT_ST() asm volatile("tcgen05.wait::st.sync.aligned;" ::: "memory")
#define TCGEN05_FENCE_BEFORE() asm volatile("tcgen05.fence::before_thread_sync;" ::: "memory")
#define TCGEN05_FENCE_AFTER()  asm volatile("tcgen05.fence::after_thread_sync;" ::: "memory")
#define TCGEN05_COMMIT(mbar) \
    asm volatile("tcgen05.commit.cta_group::1.mbarrier::arrive::one.shared::cluster.b64 [%0];" \
                 :: "r"((uint32_t)(mbar)) : "memory")
#define FENCE_PROXY_ASYNC() asm volatile("fence.proxy.async.shared::cta;" ::: "memory")
#define MBARRIER_INIT(mbar, cnt) \
    asm volatile("mbarrier.init.shared.b64 [%0], %1;" :: "r"((uint32_t)(mbar)), "r"((uint32_t)(cnt)) : "memory")
#define MBARRIER_INVAL(mbar) \
    asm volatile("mbarrier.inval.shared.b64 [%0];" :: "r"((uint32_t)(mbar)) : "memory")
#define NAMED_BAR(id) asm volatile("bar.sync %0, 128;" :: "r"(id) : "memory")
#define MBARRIER_WAIT_PARITY(mbar, parity) do { \
    uint32_t _m = (uint32_t)(mbar); uint32_t _p = (uint32_t)(parity); uint32_t _d; \
    asm volatile("{\n\t.reg .pred p;\n\tmbarrier.try_wait.parity.acquire.cta.shared::cta.b64 p, [%1], %2;\n\tselp.b32 %0, 1, 0, p;\n\t}" \
                 : "=r"(_d) : "r"(_m), "r"(_p) : "memory"); \
    if (!_d) { \
        asm volatile("{\n\t.reg .pred P1;\n\tWL_%=: \n\tmbarrier.try_wait.parity.acquire.cta.shared::cta.b64 P1, [%0], %1, 0x989680;\n\t@P1 bra.uni WD_%=;\n\tbra.uni WL_%=;\n\tWD_%=: \n\t}" \
                     :: "r"(_m), "r"(_p) : "memory"); \
    } } while (0)

// TS form: A from TMEM
#define TCGEN05_MMA_F16(d_tmem, a_tmem, b_desc, idesc, enable_d) do { \
    uint32_t _en = (enable_d) ? 1u : 0u; uint32_t _z = 0u; \
    asm volatile("{\n\t.reg .pred p;\n\tsetp.ne.u32 p, %6, 0;\n\t" \
                 "tcgen05.mma.cta_group::1.kind::f16 [%0], [%1], %2, %3, {%4, %4, %4, %4}, p;\n\t}" \
                 :: "r"(d_tmem), "r"(a_tmem), "l"(b_desc), "r"(idesc), \
                    "r"(_z), "r"(_z), "r"(_en) : "memory"); \
} while (0)

// SS form: A from SMEM via descriptor
#define TCGEN05_MMA_F16_SS(d_tmem, a_desc, b_desc, idesc, enable_d) do { \
    uint32_t _en = (enable_d) ? 1u : 0u; uint32_t _z = 0u; \
    asm volatile("{\n\t.reg .pred p;\n\tsetp.ne.u32 p, %6, 0;\n\t" \
                 "tcgen05.mma.cta_group::1.kind::f16 [%0], %1, %2, %3, {%4, %4, %4, %4}, p;\n\t}" \
                 :: "r"(d_tmem), "l"(a_desc), "l"(b_desc), "r"(idesc), \
                    "r"(_z), "r"(_z), "r"(_en) : "memory"); \
} while (0)

#define TCGEN05_ST_X16(tmem_addr, r) \
    asm volatile("tcgen05.st.sync.aligned.32x32b.x16.b32 [%0], " \
                 "{%1,%2,%3,%4,%5,%6,%7,%8,%9,%10,%11,%12,%13,%14,%15,%16};" \
                 :: "r"(tmem_addr), \
                    "r"((r)[0]), "r"((r)[1]), "r"((r)[2]), "r"((r)[3]), \
                    "r"((r)[4]), "r"((r)[5]), "r"((r)[6]), "r"((r)[7]), \
                    "r"((r)[8]), "r"((r)[9]), "r"((r)[10]), "r"((r)[11]), \
                    "r"((r)[12]), "r"((r)[13]), "r"((r)[14]), "r"((r)[15]) : "memory")

#define TCGEN05_LD_X32(r, tmem_addr) \
    asm volatile("tcgen05.ld.sync.aligned.32x32b.x32.b32 " \
                 "{%0,%1,%2,%3,%4,%5,%6,%7,%8,%9,%10,%11,%12,%13,%14,%15," \
                 "%16,%17,%18,%19,%20,%21,%22,%23,%24,%25,%26,%27,%28,%29,%30,%31}, [%32];" \
                 : "=r"((r)[0]), "=r"((r)[1]), "=r"((r)[2]), "=r"((r)[3]), \
                   "=r"((r)[4]), "=r"((r)[5]), "=r"((r)[6]), "=r"((r)[7]), \
                   "=r"((r)[8]), "=r"((r)[9]), "=r"((r)[10]), "=r"((r)[11]), \
                   "=r"((r)[12]), "=r"((r)[13]), "=r"((r)[14]), "=r"((r)[15]), \
                   "=r"((r)[16]), "=r"((r)[17]), "=r"((r)[18]), "=r"((r)[19]), \
                   "=r"((r)[20]), "=r"((r)[21]), "=r"((r)[22]), "=r"((r)[23]), \
                   "=r"((r)[24]), "=r"((r)[25]), "=r"((r)[26]), "=r"((r)[27]), \
                   "=r"((r)[28]), "=r"((r)[29]), "=r"((r)[30]), "=r"((r)[31]) \
                 : "r"(tmem_addr))

static constexpr uint64_t SMEM_DESC_BASE_SW128 =
    (uint64_t(2) << 61) | (uint64_t(1) << 46) | (uint64_t(64) << 32) | (uint64_t(1) << 16);
#define MAKE_SMEM_DESC(base_addr) (SMEM_DESC_BASE_SW128 | ((uint64_t)((base_addr) >> 4) & 0x3FFF))
// idesc kind::f16: dtype=F32, atype=btype=BF16, N=128, M=128
#define MMA_IDESC 0x8200490u
#else
static __device__ __forceinline__ void mma_bf16(float C[4], uint4 A, uint32_t b0, uint32_t b1) {
    asm("mma.sync.aligned.m16n8k16.row.col.f32.bf16.bf16.f32 "
        "{%0,%1,%2,%3}, {%4,%5,%6,%7}, {%8,%9}, {%0,%1,%2,%3};"
        : "+f"(C[0]), "+f"(C[1]), "+f"(C[2]), "+f"(C[3])
        : "r"(A.x), "r"(A.y), "r"(A.z), "r"(A.w), "r"(b0), "r"(b1));
}
#endif

// ---------------- weight pre-pack (format matches the arch branch) ----------------
__global__ void prep_weights(const float* __restrict__ Ws) {
    int t = blockIdx.x * blockDim.x + threadIdx.x;
#if USE_TC05
    if (t >= NLAYERS * 128 * 64) return;
    int kp = t & 63;          // k pair index
    int n = (t >> 6) & 127;   // N row
    int l = t >> 13;
    int k = kp * 2;
    const float* W = Ws + l * 16384;
    float w0 = W[k * 128 + n], w1 = W[(k + 1) * 128 + n];
    float h0 = bf16_round(w0), h1 = bf16_round(w1);
    uint32_t hi = pack2(h0, h1);
    uint32_t lo = pack2(w0 - h0, w1 - h1);
    int atom_row = n >> 3, inner_row = n & 7, atom_col = k >> 6, inner_col = k & 63;
    uint32_t byte = (uint32_t)(atom_row + atom_col * 16) * 1024u + inner_row * 128u + inner_col * 2u;
    uint32_t sw = byte ^ ((byte >> 3) & 0x70);
    char* base = (char*)g_W + (size_t)l * 65536;
    *(uint32_t*)(base + sw) = hi;
    *(uint32_t*)(base + 32768 + sw) = lo;
#else
    if (t >= NLAYERS * 4096) return;
    int lane = t & 31;
    int nt = (t >> 5) & 15;
    int kt = (t >> 9) & 7;
    int l = t >> 12;
    int c = lane & 3, g = lane >> 2;
    int n = nt * 8 + g;
    const float* W = Ws + l * 128 * 128;
    int k0 = kt * 16 + 2 * c;
    float w00 = W[(k0 + 0) * 128 + n];
    float w01 = W[(k0 + 1) * 128 + n];
    float w10 = W[(k0 + 8) * 128 + n];
    float w11 = W[(k0 + 9) * 128 + n];
    float h00 = bf16_round(w00), h01 = bf16_round(w01);
    float h10 = bf16_round(w10), h11 = bf16_round(w11);
    uint4 v;
    v.x = pack2(h00, h01);
    v.y = pack2(h10, h11);
    v.z = pack2(w00 - h00, w01 - h01);
    v.w = pack2(w10 - h10, w11 - h11);
    g_W[t] = v;
#endif
}

// ---------------- tcgen05 smem layout ----------------
#define OFF_WBUF   0        // 2 x 65536 (Whi 32KB + Wlo 32KB per buffer)
#define OFF_AHI    131072   // 2 x 32768 (A hi, tile0/tile1, SW128 blocked)
#define OFF_BS     196608   // 1920 f
#define OFF_W1     204288   // 256 f
#define OFF_B1     205312   // 128 f
#define OFF_W17    205824   // 128 f
#define OFF_B17    206336   // 16
#define OFF_MBAR   206352   // 2 x u64
#define OFF_TPTR   206368
#define SMEM_TC05  206384
// legacy path needs 206352; take max
#define SMEM_BYTES_MAX 206384

// TMEM column map (512 cols allocated, 384 used)
#define TM_D0   0
#define TM_D1   128
#define TM_LO0  256
#define TM_LO1  320

__global__ void __launch_bounds__(256, 1)
mlp_kernel(const float* __restrict__ x,
           const float* __restrict__ W1,
           const float* __restrict__ b1,
           const float* __restrict__ bs,
           const float* __restrict__ W17,
           const float* __restrict__ b17,
           float* __restrict__ out) {
#if USE_TC05
    // ==== tcgen05: tile-parallel epilogues (warps 0-3 tile0, warps 4-7 tile1) ====
    extern __shared__ char smem[];
    uint4* wbuf = (uint4*)smem;
    float* s_bs = (float*)(smem + OFF_BS);
    float* s_W1 = (float*)(smem + OFF_W1);
    float* s_b1 = (float*)(smem + OFF_B1);
    float* s_W17 = (float*)(smem + OFF_W17);
    float* s_b17 = (float*)(smem + OFF_B17);

    const uint32_t sb = smem_to_u32(smem);

    const int tid = threadIdx.x;
    const int w = tid >> 5;
    const int lane = tid & 31;
    const int sub = w & 3;       // TMEM subpartition (= warpid % 4)
    const int grp = w >> 2;      // tile group: warps 0-3 -> tile0, 4-7 -> tile1
    const uint32_t toff = (uint32_t)sub << 21;
    const int p = sub * 32 + lane;              // point row within tile (TMEM lane)
    const uint32_t rowbase = (uint32_t)(p >> 3) * 1024u + (uint32_t)(p & 7) * 128u;

    const uint32_t mbar_g = sb + OFF_MBAR + grp * 8;
    const uint32_t tmD  = grp ? TM_D1 : TM_D0;
    const uint32_t tmLO = grp ? TM_LO1 : TM_LO0;

    for (int i = tid; i < NLAYERS * 128; i += 256) s_bs[i] = bs[i];
    s_W1[tid] = W1[tid];
    if (tid < 128) { s_b1[tid] = b1[tid]; s_W17[tid] = W17[tid]; }
    if (tid == 0) {
        s_b17[0] = b17[0];
        MBARRIER_INIT(sb + OFF_MBAR, 1);
        MBARRIER_INIT(sb + OFF_MBAR + 8, 1);
    }
#pragma unroll
    for (int i = 0; i < 16; i++)
        wbuf[i * 256 + tid] = g_W[i * 256 + tid];

    if (w == 0) TCGEN05_ALLOC(sb + OFF_TPTR, 512);
    FENCE_PROXY_ASYNC();
    __syncthreads();
    uint32_t tmem;
    asm volatile("ld.shared.b32 %0, [%1];" : "=r"(tmem) : "r"(sb + OFF_TPTR));

    // ---- fc1: relu(x@W1+b1); hi -> SMEM (SW128), lo -> TMEM ----
    {
        const int row = blockIdx.x * 256 + grp * 128 + p;
        const float2 xv = ((const float2*)x)[row];
        const uint32_t loT = tmem + tmLO + toff;
        char* aBase = smem + OFF_AHI + grp * 32768;
#pragma unroll
        for (int cc = 0; cc < 4; cc++) {
            uint32_t rh[16], rl[16];
#pragma unroll
            for (int j = 0; j < 16; j++) {
                int n0 = cc * 32 + 2 * j;
                float v0 = fmaxf(fmaf(xv.y, s_W1[128 + n0], fmaf(xv.x, s_W1[n0], s_b1[n0])), 0.f);
                float v1 = fmaxf(fmaf(xv.y, s_W1[128 + n0 + 1], fmaf(xv.x, s_W1[n0 + 1], s_b1[n0 + 1])), 0.f);
                float h0 = bf16_round(v0), h1 = bf16_round(v1);
                rh[j] = pack2(h0, h1);
                rl[j] = pack2(v0 - h0, v1 - h1);
            }
            // hi -> SMEM: atom_col = cc>>1, inner 64-byte half = (cc&1)*64
#pragma unroll
            for (int j = 0; j < 4; j++) {
                uint32_t byte = rowbase + (uint32_t)(cc >> 1) * 16384u + (uint32_t)((cc & 1) * 64 + j * 16);
                uint32_t sw = byte ^ ((byte >> 3) & 0x70);
                *(uint4*)(aBase + sw) = make_uint4(rh[4 * j], rh[4 * j + 1], rh[4 * j + 2], rh[4 * j + 3]);
            }
            TCGEN05_ST_X16(loT + cc * 16, rl);
        }
        TCGEN05_WAIT_ST();
    }
    TCGEN05_FENCE_BEFORE();
    FENCE_PROXY_ASYNC();
    __syncthreads();

    const uint32_t OFFS[8] = {0, 2, 4, 6, 1024, 1026, 1028, 1030};

    // ---- issue layer 0 MMAs for both tiles (warp 0) ----
    if (w == 0) {
        TCGEN05_FENCE_AFTER();
        if (elect_one_pred()) {
            uint64_t dh = MAKE_SMEM_DESC(sb + OFF_WBUF);
            uint64_t dl = dh + 2048;
#pragma unroll
            for (int t2 = 0; t2 < 2; t2++) {
                uint32_t D = tmem + (t2 ? TM_D1 : TM_D0);
                uint32_t lo = tmem + (t2 ? TM_LO1 : TM_LO0);
                uint64_t ad = MAKE_SMEM_DESC(sb + OFF_AHI + t2 * 32768);
#pragma unroll
                for (int s = 0; s < 8; s++)
                    TCGEN05_MMA_F16_SS(D, ad + OFFS[s], dh + OFFS[s], MMA_IDESC, s > 0);
#pragma unroll
                for (int s = 0; s < 8; s++)
                    TCGEN05_MMA_F16_SS(D, ad + OFFS[s], dl + OFFS[s], MMA_IDESC, true);
#pragma unroll
                for (int s = 0; s < 8; s++)
                    TCGEN05_MMA_F16(D, lo + s * 8, dh + OFFS[s], MMA_IDESC, true);
                TCGEN05_COMMIT(sb + OFF_MBAR + t2 * 8);
            }
        }
    }

    // prefetch layer-1 weights while layer-0 MMA runs; sync for cross-group visibility
    {
        const uint4* src = g_W + 4096;
        uint4* dst = wbuf + 4096;
#pragma unroll
        for (int i = 0; i < 16; i++)
            dst[i * 256 + tid] = src[i * 256 + tid];
    }
    FENCE_PROXY_ASYNC();
    __syncthreads();

    const uint32_t Dbase = tmem + tmD + toff;
    const uint32_t loT = tmem + tmLO + toff;
    char* aBase = smem + OFF_AHI + grp * 32768;
    const uint64_t adesc = MAKE_SMEM_DESC(sb + OFF_AHI + grp * 32768);

    // ---- fc2..fc16, tile-parallel ----
    for (int l = 0; l < NLAYERS; l++) {
        const uint32_t ph = (uint32_t)(l & 1);
        const bool last = (l == NLAYERS - 1);
        const float* bias = s_bs + l * 128;
        const uint64_t dh_next = MAKE_SMEM_DESC(sb + OFF_WBUF + ((l + 1) & 1) * 65536);
        const uint64_t dl_next = dh_next + 2048;

        MBARRIER_WAIT_PARITY(mbar_g, ph);
        TCGEN05_FENCE_AFTER();

        float facc = 0.f;
#pragma unroll
        for (int c = 0; c < 2; c++) {
            uint32_t vr0[32], vr1[32];
            TCGEN05_LD_X32(vr0, Dbase + c * 64);
            TCGEN05_LD_X32(vr1, Dbase + c * 64 + 32);
            TCGEN05_WAIT_LD();
            float v0[32], v1[32];
#pragma unroll
            for (int j = 0; j < 32; j++) {
                v0[j] = fmaxf(__uint_as_float(vr0[j]) + bias[c * 64 + j], 0.f);
                v1[j] = fmaxf(__uint_as_float(vr1[j]) + bias[c * 64 + 32 + j], 0.f);
            }
            if (!last) {
                uint32_t rh[32], rl[32];
#pragma unroll
                for (int j = 0; j < 16; j++) {
                    float h0 = bf16_round(v0[2 * j]), h1 = bf16_round(v0[2 * j + 1]);
                    rh[j] = pack2(h0, h1);
                    rl[j] = pack2(v0[2 * j] - h0, v0[2 * j + 1] - h1);
                    float g0 = bf16_round(v1[2 * j]), g1 = bf16_round(v1[2 * j + 1]);
                    rh[16 + j] = pack2(g0, g1);
                    rl[16 + j] = pack2(v1[2 * j] - g0, v1[2 * j + 1] - g1);
                }
                // hi -> SMEM A tile (atom_col = c), 128 bytes of this row
#pragma unroll
                for (int j = 0; j < 8; j++) {
                    uint32_t byte = rowbase + (uint32_t)c * 16384u + (uint32_t)(j * 16);
                    uint32_t sw = byte ^ ((byte >> 3) & 0x70);
                    *(uint4*)(aBase + sw) = make_uint4(rh[4 * j], rh[4 * j + 1], rh[4 * j + 2], rh[4 * j + 3]);
                }
                // lo -> TMEM (32 bf16x2 cols per chunk)
                TCGEN05_ST_X16(loT + c * 32, rl);
                TCGEN05_ST_X16(loT + c * 32 + 16, rl + 16);
            } else {
#pragma unroll
                for (int j = 0; j < 32; j++) {
                    facc = fmaf(v0[j], s_W17[c * 64 + j], facc);
                    facc = fmaf(v1[j], s_W17[c * 64 + 32 + j], facc);
                }
            }
        }

        if (!last) {
            TCGEN05_WAIT_ST();
            TCGEN05_FENCE_BEFORE();
            FENCE_PROXY_ASYNC();
            NAMED_BAR(grp + 1);
            // group leader issues next layer's MMA for this tile
            if (sub == 0) {
                TCGEN05_FENCE_AFTER();
                if (elect_one_pred()) {
                    uint32_t D = tmem + tmD;
                    uint32_t lo2 = tmem + tmLO;
#pragma unroll
                    for (int s = 0; s < 8; s++)
                        TCGEN05_MMA_F16_SS(D, adesc + OFFS[s], dh_next + OFFS[s], MMA_IDESC, s > 0);
#pragma unroll
                    for (int s = 0; s < 8; s++)
                        TCGEN05_MMA_F16_SS(D, adesc + OFFS[s], dl_next + OFFS[s], MMA_IDESC, true);
#pragma unroll
                    for (int s = 0; s < 8; s++)
                        TCGEN05_MMA_F16(D, lo2 + s * 8, dh_next + OFFS[s], MMA_IDESC, true);
                    TCGEN05_COMMIT(mbar_g);
                }
            }
            // prefetch weights for layer l+2 into the buffer MMA(l) just finished with
            if (l + 2 < NLAYERS) {
                const uint4* src = g_W + (l + 2) * 4096;
                uint4* dst = wbuf + (l & 1) * 4096;
#pragma unroll
                for (int i = 0; i < 16; i++)
                    dst[i * 256 + tid] = src[i * 256 + tid];
            }
            FENCE_PROXY_ASYNC();
            __syncthreads();   // both MMA(l) proven done; prefetch visible to both groups
        } else {
            out[blockIdx.x * 256 + grp * 128 + p] = facc + s_b17[0];
        }
    }

    __syncthreads();
    if (tid == 0) {
        MBARRIER_INVAL(sb + OFF_MBAR);
        MBARRIER_INVAL(sb + OFF_MBAR + 8);
    }
    if (w == 0) {
        TCGEN05_RELINQUISH();
        TCGEN05_DEALLOC(tmem, 512);
    }
#else
    // ================= legacy HMMA implementation (compiles on base sm_103) =================
    extern __shared__ uint4 smem[];
    uint4* Wsm = smem;
    uint4* Hhi = smem + 4096;
    uint4* Hlo = smem + 8192;
    float* s_W1 = (float*)(smem + 12288);
    float* s_b1 = s_W1 + 256;
    float* s_bs = s_b1 + 128;
    float* s_W17 = s_bs + NLAYERS * 128;
    float* s_b17 = s_W17 + 128;

    const int tid = threadIdx.x;
    const int w = tid >> 5;
    const int lane = tid & 31;
    const int g = lane >> 2;
    const int c = lane & 3;

    s_W1[tid] = W1[tid];
    if (tid < 128) { s_b1[tid] = b1[tid]; s_W17[tid] = W17[tid]; }
    for (int i = tid; i < NLAYERS * 128; i += 256) s_bs[i] = bs[i];
    if (tid == 0) s_b17[0] = b17[0];
    __syncthreads();

    const int base_m = blockIdx.x * 256 + w * 32;

#pragma unroll
    for (int mt = 0; mt < 2; mt++) {
        int r0 = base_m + mt * 16 + g;
        float2 xa = *((const float2*)x + r0);
        float2 xb = *((const float2*)x + r0 + 8);
#pragma unroll
        for (int kt = 0; kt < 8; kt++) {
            float va[4], vb[4];
#pragma unroll
            for (int e = 0; e < 4; e++) {
                int j = kt * 16 + 2 * c + (e >> 1) * 8 + (e & 1);
                float w0 = s_W1[j], w1 = s_W1[128 + j], bb = s_b1[j];
                va[e] = fmaxf(fmaf(xa.y, w1, fmaf(xa.x, w0, bb)), 0.0f);
                vb[e] = fmaxf(fmaf(xb.y, w1, fmaf(xb.x, w0, bb)), 0.0f);
            }
            float ha[4], hb[4];
#pragma unroll
            for (int e = 0; e < 4; e++) { ha[e] = bf16_round(va[e]); hb[e] = bf16_round(vb[e]); }
            uint4 vh, vl;
            vh.x = pack2(ha[0], ha[1]); vh.y = pack2(hb[0], hb[1]);
            vh.z = pack2(ha[2], ha[3]); vh.w = pack2(hb[2], hb[3]);
            vl.x = pack2(va[0] - ha[0], va[1] - ha[1]);
            vl.y = pack2(vb[0] - hb[0], vb[1] - hb[1]);
            vl.z = pack2(va[2] - ha[2], va[3] - ha[3]);
            vl.w = pack2(vb[2] - hb[2], vb[3] - hb[3]);
            int hidx = ((w * 2 + mt) * 8 + kt) * 32 + lane;
            Hhi[hidx] = vh; Hlo[hidx] = vl;
        }
    }

    float C[2][16][4];

    for (int l = 0; l < NLAYERS; l++) {
        __syncthreads();
        {
            const uint4* Wp = g_W + l * 4096;
#pragma unroll
            for (int i = 0; i < 16; i++)
                Wsm[i * 256 + tid] = Wp[i * 256 + tid];
        }
        __syncthreads();

        const float* bias = s_bs + l * 128;
#pragma unroll
        for (int nt = 0; nt < 16; nt++) {
            float bb0 = bias[nt * 8 + 2 * c];
            float bb1 = bias[nt * 8 + 2 * c + 1];
#pragma unroll
            for (int mt = 0; mt < 2; mt++) {
                C[mt][nt][0] = bb0; C[mt][nt][1] = bb1;
                C[mt][nt][2] = bb0; C[mt][nt][3] = bb1;
            }
        }

#pragma unroll 2
        for (int kt = 0; kt < 8; kt++) {
            uint4 Ah[2], Al[2];
#pragma unroll
            for (int mt = 0; mt < 2; mt++) {
                int hidx = ((w * 2 + mt) * 8 + kt) * 32 + lane;
                Ah[mt] = Hhi[hidx]; Al[mt] = Hlo[hidx];
            }
#pragma unroll
            for (int nt = 0; nt < 16; nt++) {
                uint4 B = Wsm[(kt * 16 + nt) * 32 + lane];
#pragma unroll
                for (int mt = 0; mt < 2; mt++) {
                    mma_bf16(C[mt][nt], Ah[mt], B.x, B.y);
                    mma_bf16(C[mt][nt], Al[mt], B.x, B.y);
                    mma_bf16(C[mt][nt], Ah[mt], B.z, B.w);
                }
            }
        }

#pragma unroll
        for (int mt = 0; mt < 2; mt++)
#pragma unroll
            for (int nt = 0; nt < 16; nt++)
#pragma unroll
                for (int e = 0; e < 4; e++)
                    C[mt][nt][e] = fmaxf(C[mt][nt][e], 0.0f);

        if (l < NLAYERS - 1) {
#pragma unroll
            for (int mt = 0; mt < 2; mt++)
#pragma unroll
                for (int ktp = 0; ktp < 8; ktp++) {
                    const float* c0 = C[mt][2 * ktp];
                    const float* c1 = C[mt][2 * ktp + 1];
                    float h0 = bf16_round(c0[0]), h1 = bf16_round(c0[1]);
                    float h2 = bf16_round(c0[2]), h3 = bf16_round(c0[3]);
                    float h4 = bf16_round(c1[0]), h5 = bf16_round(c1[1]);
                    float h6 = bf16_round(c1[2]), h7 = bf16_round(c1[3]);
                    uint4 vh, vl;
                    vh.x = pack2(h0, h1); vh.y = pack2(h2, h3);
                    vh.z = pack2(h4, h5); vh.w = pack2(h6, h7);
                    vl.x = pack2(c0[0] - h0, c0[1] - h1);
                    vl.y = pack2(c0[2] - h2, c0[3] - h3);
                    vl.z = pack2(c1[0] - h4, c1[1] - h5);
                    vl.w = pack2(c1[2] - h6, c1[3] - h7);
                    int hidx = ((w * 2 + mt) * 8 + ktp) * 32 + lane;
                    Hhi[hidx] = vh; Hlo[hidx] = vl;
                }
        }
    }

    float acc[4] = {0.f, 0.f, 0.f, 0.f};
#pragma unroll
    for (int nt = 0; nt < 16; nt++) {
        float w0 = s_W17[nt * 8 + 2 * c];
        float w1 = s_W17[nt * 8 + 2 * c + 1];
#pragma unroll
        for (int mt = 0; mt < 2; mt++) {
            acc[mt * 2 + 0] = fmaf(C[mt][nt][0], w0, fmaf(C[mt][nt][1], w1, acc[mt * 2 + 0]));
            acc[mt * 2 + 1] = fmaf(C[mt][nt][2], w0, fmaf(C[mt][nt][3], w1, acc[mt * 2 + 1]));
        }
    }
#pragma unroll
    for (int i = 0; i < 4; i++) {
        acc[i] += __shfl_xor_sync(0xffffffffu, acc[i], 1);
        acc[i] += __shfl_xor_sync(0xffffffffu, acc[i], 2);
    }
    if (c == 0) {
        float bb = s_b17[0];
        out[base_m + g]          = acc[0] + bb;
        out[base_m + g + 8]      = acc[1] + bb;
        out[base_m + 16 + g]     = acc[2] + bb;
        out[base_m + 16 + g + 8] = acc[3] + bb;
    }
#endif
}

extern "C" void kernel_launch(void* const* d_in, const int* in_sizes, int n_in,
                              void* d_out, int out_size) {
    const float* x   = (const float*)d_in[0];
    const float* W1  = (const float*)d_in[1];
    const float* b1  = (const float*)d_in[2];
    const float* Ws  = (const float*)d_in[3];
    const float* bs  = (const float*)d_in[4];
    const float* W17 = (const float*)d_in[5];
    const float* b17 = (const float*)d_in[6];
    float* out = (float*)d_out;

    int nPoints = in_sizes[0] / 2;  // 1048576

    cudaFuncSetAttribute(mlp_kernel, cudaFuncAttributeMaxDynamicSharedMemorySize, SMEM_BYTES_MAX);

    prep_weights<<<480, 256>>>(Ws);
    mlp_kernel<<<nPoints / 256, 256, SMEM_BYTES_MAX>>>(x, W1, b1, bs, W17, b17, out);
}

// round 7
// speedup vs baseline: 1.3101x; 1.3101x over previous
#include <cuda_runtime.h>
#include <cuda_bf16.h>
#include <cstdint>

#define NLAYERS 15

// ---- arch-feature gate: tcgen05 only exists on sm_103a/'f' feature targets ----
#if defined(__CUDA_ARCH__)
#  if defined(__CUDA_ARCH_FEAT_SM103_ALL) || defined(__CUDA_ARCH_FEAT_SM100_ALL) || defined(__CUDA_ARCH_FAMILY_SPECIFIC__)
#    define USE_TC05 1
#  else
#    define USE_TC05 0
#  endif
#else
#  define USE_TC05 0
#endif

// ---------------- common helpers ----------------
static __device__ __forceinline__ uint32_t pack2(float e0, float e1) {
    uint32_t r;
    asm("cvt.rn.bf16x2.f32 %0, %1, %2;" : "=r"(r) : "f"(e1), "f"(e0));
    return r;
}
static __device__ __forceinline__ float bf16_round(float a) {
    return __bfloat162float(__float2bfloat16_rn(a));
}

// One global weight image; format depends on which branch compiled (both are 15*4096 uint4).
__device__ uint4 g_W[NLAYERS * 4096];

#if USE_TC05
__device__ __forceinline__ uint32_t elect_one_pred() {
    uint32_t pred;
    asm volatile("{\n\t.reg .pred p;\n\telect.sync _|p, 0xFFFFFFFF;\n\tselp.b32 %0, 1, 0, p;\n\t}"
                 : "=r"(pred));
    return pred;
}
#endif
__device__ __forceinline__ uint32_t smem_to_u32(const void* p) {
    uint32_t a;
    asm("{ .reg .u64 t; cvta.to.shared.u64 t, %1; cvt.u32.u64 %0, t; }" : "=r"(a) : "l"(p));
    return a;
}

#if USE_TC05
#define TCGEN05_ALLOC(smem_result_addr, nCols) \
    asm volatile("tcgen05.alloc.cta_group::1.sync.aligned.shared::cta.b32 [%0], %1;" \
                 :: "r"((uint32_t)(smem_result_addr)), "r"((uint32_t)(nCols)) : "memory")
#define TCGEN05_DEALLOC(tmem_addr, nCols) \
    asm volatile("tcgen05.dealloc.cta_group::1.sync.aligned.b32 %0, %1;" :: "r"(tmem_addr), "r"((uint32_t)(nCols)))
#define TCGEN05_RELINQUISH() \
    asm volatile("tcgen05.relinquish_alloc_permit.cta_group::1.sync.aligned;")
#define TCGEN05_WAIT_LD() asm volatile("tcgen05.wait::ld.sync.aligned;" ::: "memory")
#define TCGEN05_WAIT_ST() asm volatile("tcgen05.wait::st.sync.aligned;" ::: "memory")
#define TCGEN05_FENCE_BEFORE() asm volatile("tcgen05.fence::before_thread_sync;" ::: "memory")
#define TCGEN05_FENCE_AFTER()  asm volatile("tcgen05.fence::after_thread_sync;" ::: "memory")
#define TCGEN05_COMMIT(mbar) \
    asm volatile("tcgen05.commit.cta_group::1.mbarrier::arrive::one.shared::cluster.b64 [%0];" \
                 :: "r"((uint32_t)(mbar)) : "memory")
#define FENCE_PROXY_ASYNC() asm volatile("fence.proxy.async.shared::cta;" ::: "memory")
#define MBARRIER_INIT(mbar, cnt) \
    asm volatile("mbarrier.init.shared.b64 [%0], %1;" :: "r"((uint32_t)(mbar)), "r"((uint32_t)(cnt)) : "memory")
#define MBARRIER_INVAL(mbar) \
    asm volatile("mbarrier.inval.shared.b64 [%0];" :: "r"((uint32_t)(mbar)) : "memory")
#define MBARRIER_EXPECT_TX(mbar, bytes) \
    asm volatile("mbarrier.arrive.expect_tx.shared.b64 _, [%0], %1;" \
                 :: "r"((uint32_t)(mbar)), "r"((uint32_t)(bytes)) : "memory")
#define CP_BULK_G2S(dst_smem, src_gmem, nbytes, mbar) \
    asm volatile("cp.async.bulk.shared::cta.global.mbarrier::complete_tx::bytes [%0], [%1], %2, [%3];" \
                 :: "r"((uint32_t)(dst_smem)), "l"(src_gmem), "r"((uint32_t)(nbytes)), \
                    "r"((uint32_t)(mbar)) : "memory")
#define MBARRIER_WAIT_PARITY(mbar, parity) do { \
    uint32_t _m = (uint32_t)(mbar); uint32_t _p = (uint32_t)(parity); uint32_t _d; \
    asm volatile("{\n\t.reg .pred p;\n\tmbarrier.try_wait.parity.acquire.cta.shared::cta.b64 p, [%1], %2;\n\tselp.b32 %0, 1, 0, p;\n\t}" \
                 : "=r"(_d) : "r"(_m), "r"(_p) : "memory"); \
    if (!_d) { \
        asm volatile("{\n\t.reg .pred P1;\n\tWL_%=: \n\tmbarrier.try_wait.parity.acquire.cta.shared::cta.b64 P1, [%0], %1, 0x989680;\n\t@P1 bra.uni WD_%=;\n\tbra.uni WL_%=;\n\tWD_%=: \n\t}" \
                     :: "r"(_m), "r"(_p) : "memory"); \
    } } while (0)

// TS form: A from TMEM
#define TCGEN05_MMA_F16(d_tmem, a_tmem, b_desc, idesc, enable_d) do { \
    uint32_t _en = (enable_d) ? 1u : 0u; uint32_t _z = 0u; \
    asm volatile("{\n\t.reg .pred p;\n\tsetp.ne.u32 p, %6, 0;\n\t" \
                 "tcgen05.mma.cta_group::1.kind::f16 [%0], [%1], %2, %3, {%4, %4, %4, %4}, p;\n\t}" \
                 :: "r"(d_tmem), "r"(a_tmem), "l"(b_desc), "r"(idesc), \
                    "r"(_z), "r"(_z), "r"(_en) : "memory"); \
} while (0)

#define TCGEN05_ST_X16(tmem_addr, r) \
    asm volatile("tcgen05.st.sync.aligned.32x32b.x16.b32 [%0], " \
                 "{%1,%2,%3,%4,%5,%6,%7,%8,%9,%10,%11,%12,%13,%14,%15,%16};" \
                 :: "r"(tmem_addr), \
                    "r"((r)[0]), "r"((r)[1]), "r"((r)[2]), "r"((r)[3]), \
                    "r"((r)[4]), "r"((r)[5]), "r"((r)[6]), "r"((r)[7]), \
                    "r"((r)[8]), "r"((r)[9]), "r"((r)[10]), "r"((r)[11]), \
                    "r"((r)[12]), "r"((r)[13]), "r"((r)[14]), "r"((r)[15]) : "memory")

#define TCGEN05_LD_X32(r, tmem_addr) \
    asm volatile("tcgen05.ld.sync.aligned.32x32b.x32.b32 " \
                 "{%0,%1,%2,%3,%4,%5,%6,%7,%8,%9,%10,%11,%12,%13,%14,%15," \
                 "%16,%17,%18,%19,%20,%21,%22,%23,%24,%25,%26,%27,%28,%29,%30,%31}, [%32];" \
                 : "=r"((r)[0]), "=r"((r)[1]), "=r"((r)[2]), "=r"((r)[3]), \
                   "=r"((r)[4]), "=r"((r)[5]), "=r"((r)[6]), "=r"((r)[7]), \
                   "=r"((r)[8]), "=r"((r)[9]), "=r"((r)[10]), "=r"((r)[11]), \
                   "=r"((r)[12]), "=r"((r)[13]), "=r"((r)[14]), "=r"((r)[15]), \
                   "=r"((r)[16]), "=r"((r)[17]), "=r"((r)[18]), "=r"((r)[19]), \
                   "=r"((r)[20]), "=r"((r)[21]), "=r"((r)[22]), "=r"((r)[23]), \
                   "=r"((r)[24]), "=r"((r)[25]), "=r"((r)[26]), "=r"((r)[27]), \
                   "=r"((r)[28]), "=r"((r)[29]), "=r"((r)[30]), "=r"((r)[31]) \
                 : "r"(tmem_addr))

static constexpr uint64_t SMEM_DESC_BASE_SW128 =
    (uint64_t(2) << 61) | (uint64_t(1) << 46) | (uint64_t(64) << 32) | (uint64_t(1) << 16);
#define MAKE_SMEM_DESC(base_addr) (SMEM_DESC_BASE_SW128 | ((uint64_t)((base_addr) >> 4) & 0x3FFF))
// idesc kind::f16: dtype=F32, atype=btype=BF16, N=128, M=128
#define MMA_IDESC 0x8200490u
#else
static __device__ __forceinline__ void mma_bf16(float C[4], uint4 A, uint32_t b0, uint32_t b1) {
    asm("mma.sync.aligned.m16n8k16.row.col.f32.bf16.bf16.f32 "
        "{%0,%1,%2,%3}, {%4,%5,%6,%7}, {%8,%9}, {%0,%1,%2,%3};"
        : "+f"(C[0]), "+f"(C[1]), "+f"(C[2]), "+f"(C[3])
        : "r"(A.x), "r"(A.y), "r"(A.z), "r"(A.w), "r"(b0), "r"(b1));
}
#endif

// ---------------- weight pre-pack (format matches the arch branch) ----------------
__global__ void prep_weights(const float* __restrict__ Ws) {
    int t = blockIdx.x * blockDim.x + threadIdx.x;
#if USE_TC05
    if (t >= NLAYERS * 128 * 64) return;
    int kp = t & 63;          // k pair index
    int n = (t >> 6) & 127;   // N row
    int l = t >> 13;
    int k = kp * 2;
    const float* W = Ws + l * 16384;
    float w0 = W[k * 128 + n], w1 = W[(k + 1) * 128 + n];
    float h0 = bf16_round(w0), h1 = bf16_round(w1);
    uint32_t hi = pack2(h0, h1);
    uint32_t lo = pack2(w0 - h0, w1 - h1);
    int atom_row = n >> 3, inner_row = n & 7, atom_col = k >> 6, inner_col = k & 63;
    uint32_t byte = (uint32_t)(atom_row + atom_col * 16) * 1024u + inner_row * 128u + inner_col * 2u;
    uint32_t sw = byte ^ ((byte >> 3) & 0x70);
    char* base = (char*)g_W + (size_t)l * 65536;
    *(uint32_t*)(base + sw) = hi;
    *(uint32_t*)(base + 32768 + sw) = lo;
#else
    if (t >= NLAYERS * 4096) return;
    int lane = t & 31;
    int nt = (t >> 5) & 15;
    int kt = (t >> 9) & 7;
    int l = t >> 12;
    int c = lane & 3, g = lane >> 2;
    int n = nt * 8 + g;
    const float* W = Ws + l * 128 * 128;
    int k0 = kt * 16 + 2 * c;
    float w00 = W[(k0 + 0) * 128 + n];
    float w01 = W[(k0 + 1) * 128 + n];
    float w10 = W[(k0 + 8) * 128 + n];
    float w11 = W[(k0 + 9) * 128 + n];
    float h00 = bf16_round(w00), h01 = bf16_round(w01);
    float h10 = bf16_round(w10), h11 = bf16_round(w11);
    uint4 v;
    v.x = pack2(h00, h01);
    v.y = pack2(h10, h11);
    v.z = pack2(w00 - h00, w01 - h01);
    v.w = pack2(w10 - h10, w11 - h11);
    g_W[t] = v;
#endif
}

// ---------------- tcgen05 smem layout ----------------
#define OFF_WBUF   0        // 2 x 65536 (Whi 32KB + Wlo 32KB per buffer)
#define OFF_BS     131072   // 1920 f
#define OFF_W1     138752   // 256 f
#define OFF_B1     139776   // 128 f
#define OFF_W17    140288   // 128 f
#define OFF_B17    140800   // 16
#define OFF_PART   140816   // 512 f
#define OFF_MBAR   142864   // 2 x u64 (MMA commit barriers)
#define OFF_WMBAR  142880   // 2 x u64 (weight copy barriers)
#define OFF_TPTR   142896
#define SMEM_TC05  142912
// legacy path needs 206352; take max
#define SMEM_BYTES_MAX 206352

// TMEM column map (512 cols)
#define TM_D0   0
#define TM_D1   128
#define TM_A0H  256
#define TM_A0L  320
#define TM_A1H  384
#define TM_A1L  448

__global__ void __launch_bounds__(256, 1)
mlp_kernel(const float* __restrict__ x,
           const float* __restrict__ W1,
           const float* __restrict__ b1,
           const float* __restrict__ bs,
           const float* __restrict__ W17,
           const float* __restrict__ b17,
           float* __restrict__ out) {
#if USE_TC05
    // ===== tcgen05 TS, per-tile pipelined, TMA bulk weight prefetch (no proxy fences) =====
    extern __shared__ char smem[];
    float* s_bs = (float*)(smem + OFF_BS);
    float* s_W1 = (float*)(smem + OFF_W1);
    float* s_b1 = (float*)(smem + OFF_B1);
    float* s_W17 = (float*)(smem + OFF_W17);
    float* s_b17 = (float*)(smem + OFF_B17);
    float* s_part = (float*)(smem + OFF_PART);

    const uint32_t sb = smem_to_u32(smem);
    const uint32_t mbar0 = sb + OFF_MBAR;
    const uint32_t mbar1 = sb + OFF_MBAR + 8;
    const uint32_t wmbar0 = sb + OFF_WMBAR;
    const uint32_t wmbar1 = sb + OFF_WMBAR + 8;

    const int tid = threadIdx.x;
    const int w = tid >> 5;
    const int lane = tid & 31;
    const int sub = w & 3;       // TMEM subpartition (= warpid % 4)
    const int half = w >> 2;     // column half (0: cols 0-63, 1: 64-127)
    const uint32_t toff = (uint32_t)sub << 21;

    const char* gW = (const char*)g_W;

    for (int i = tid; i < NLAYERS * 128; i += 256) s_bs[i] = bs[i];
    s_W1[tid] = W1[tid];
    if (tid < 128) { s_b1[tid] = b1[tid]; s_W17[tid] = W17[tid]; }
    if (tid == 0) {
        s_b17[0] = b17[0];
        MBARRIER_INIT(mbar0, 1);
        MBARRIER_INIT(mbar1, 1);
        MBARRIER_INIT(wmbar0, 1);
        MBARRIER_INIT(wmbar1, 1);
    }
    // stage layer-0 weights via LDG (one-time; proxy fence below covers it)
    {
        const uint4* src = g_W;
        uint4* dst = (uint4*)smem;
#pragma unroll
        for (int i = 0; i < 16; i++)
            dst[i * 256 + tid] = src[i * 256 + tid];
    }
    if (w == 0) TCGEN05_ALLOC(sb + OFF_TPTR, 512);
    FENCE_PROXY_ASYNC();
    __syncthreads();
    uint32_t tmem;
    asm volatile("ld.shared.b32 %0, [%1];" : "=r"(tmem) : "r"(sb + OFF_TPTR));

    // kick off layer-1 weight bulk copy (async, completes on wmbar1 phase 0)
    if (tid == 0) {
        MBARRIER_EXPECT_TX(wmbar1, 65536);
        CP_BULK_G2S(sb + OFF_WBUF + 65536, gW + 65536, 65536, wmbar1);
    }

    // ---- fc1: relu(x@W1+b1) -> A tiles in TMEM (hi/lo bf16x2) ----
    {
        const int tile = half;
        const int row = blockIdx.x * 256 + tile * 128 + sub * 32 + lane;
        const float2 xv = ((const float2*)x)[row];
        const uint32_t aH = tmem + (tile ? TM_A1H : TM_A0H) + toff;
        const uint32_t aL = tmem + (tile ? TM_A1L : TM_A0L) + toff;
#pragma unroll
        for (int cc = 0; cc < 4; cc++) {
            uint32_t rh[16], rl[16];
#pragma unroll
            for (int j = 0; j < 16; j++) {
                int n0 = cc * 32 + 2 * j;
                float v0 = fmaxf(fmaf(xv.y, s_W1[128 + n0], fmaf(xv.x, s_W1[n0], s_b1[n0])), 0.f);
                float v1 = fmaxf(fmaf(xv.y, s_W1[128 + n0 + 1], fmaf(xv.x, s_W1[n0 + 1], s_b1[n0 + 1])), 0.f);
                float h0 = bf16_round(v0), h1 = bf16_round(v1);
                rh[j] = pack2(h0, h1);
                rl[j] = pack2(v0 - h0, v1 - h1);
            }
            TCGEN05_ST_X16(aH + cc * 16, rh);
            TCGEN05_ST_X16(aL + cc * 16, rl);
        }
        TCGEN05_WAIT_ST();
    }
    TCGEN05_FENCE_BEFORE();
    __syncthreads();

    const uint32_t OFFS[8] = {0, 2, 4, 6, 1024, 1026, 1028, 1030};

    // ---- issue layer 0 MMAs for both tiles ----
    if (w == 0) {
        TCGEN05_FENCE_AFTER();
        if (elect_one_pred()) {
            uint64_t dh = MAKE_SMEM_DESC(sb + OFF_WBUF);
            uint64_t dl = dh + 2048;
#pragma unroll
            for (int t2 = 0; t2 < 2; t2++) {
                uint32_t D = tmem + (t2 ? TM_D1 : TM_D0);
                uint32_t Ah = tmem + (t2 ? TM_A1H : TM_A0H);
                uint32_t Al = tmem + (t2 ? TM_A1L : TM_A0L);
#pragma unroll
                for (int s = 0; s < 8; s++)
                    TCGEN05_MMA_F16(D, Ah + s * 8, dh + OFFS[s], MMA_IDESC, s > 0);
#pragma unroll
                for (int s = 0; s < 8; s++)
                    TCGEN05_MMA_F16(D, Al + s * 8, dh + OFFS[s], MMA_IDESC, true);
#pragma unroll
                for (int s = 0; s < 8; s++)
                    TCGEN05_MMA_F16(D, Ah + s * 8, dl + OFFS[s], MMA_IDESC, true);
                TCGEN05_COMMIT(t2 ? mbar1 : mbar0);
            }
        }
    }

    float acc0 = 0.f, acc1 = 0.f;
    int wph0 = 0, wph1 = 0;   // weight-copy mbar phases (used by warp 0 only)

    // ---- fc2..fc16, per-tile pipelined ----
    for (int l = 0; l < NLAYERS; l++) {
        const uint32_t ph = (uint32_t)(l & 1);
        const bool last = (l == NLAYERS - 1);
        const float* bias = s_bs + l * 128;
        const uint64_t dh_next = MAKE_SMEM_DESC(sb + OFF_WBUF + ((l + 1) & 1) * 65536);
        const uint64_t dl_next = dh_next + 2048;

#pragma unroll
        for (int t2 = 0; t2 < 2; t2++) {
            const uint32_t mbar = t2 ? mbar1 : mbar0;
            MBARRIER_WAIT_PARITY(mbar, ph);
            TCGEN05_FENCE_AFTER();
            const uint32_t Dbase = tmem + (t2 ? TM_D1 : TM_D0) + toff;
            const uint32_t aH = tmem + (t2 ? TM_A1H : TM_A0H) + toff;
            const uint32_t aL = tmem + (t2 ? TM_A1L : TM_A0L) + toff;
            const int col0 = half * 64;

            uint32_t vr0[32], vr1[32];
            TCGEN05_LD_X32(vr0, Dbase + col0);
            TCGEN05_LD_X32(vr1, Dbase + col0 + 32);
            TCGEN05_WAIT_LD();

            float v0[32], v1[32];
#pragma unroll
            for (int j = 0; j < 32; j++) {
                v0[j] = fmaxf(__uint_as_float(vr0[j]) + bias[col0 + j], 0.f);
                v1[j] = fmaxf(__uint_as_float(vr1[j]) + bias[col0 + 32 + j], 0.f);
            }

            if (!last) {
                uint32_t rh0[16], rl0[16], rh1[16], rl1[16];
#pragma unroll
                for (int j = 0; j < 16; j++) {
                    float h0 = bf16_round(v0[2 * j]), h1 = bf16_round(v0[2 * j + 1]);
                    rh0[j] = pack2(h0, h1);
                    rl0[j] = pack2(v0[2 * j] - h0, v0[2 * j + 1] - h1);
                    float g0 = bf16_round(v1[2 * j]), g1 = bf16_round(v1[2 * j + 1]);
                    rh1[j] = pack2(g0, g1);
                    rl1[j] = pack2(v1[2 * j] - g0, v1[2 * j + 1] - g1);
                }
                TCGEN05_ST_X16(aH + (col0 >> 1), rh0);
                TCGEN05_ST_X16(aL + (col0 >> 1), rl0);
                TCGEN05_ST_X16(aH + (col0 >> 1) + 16, rh1);
                TCGEN05_ST_X16(aL + (col0 >> 1) + 16, rl1);
                TCGEN05_WAIT_ST();
                TCGEN05_FENCE_BEFORE();
                __syncthreads();
                // issue next layer's MMA for THIS tile while the other tile's epilogue runs
                if (w == 0) {
                    if (t2 == 0) {
                        // ensure next layer's weight buffer arrived (fast path after 1-layer lead)
                        if ((l + 1) & 1) { MBARRIER_WAIT_PARITY(wmbar1, wph1); wph1 ^= 1; }
                        else             { MBARRIER_WAIT_PARITY(wmbar0, wph0); wph0 ^= 1; }
                    }
                    TCGEN05_FENCE_AFTER();
                    if (elect_one_pred()) {
                        uint32_t D = tmem + (t2 ? TM_D1 : TM_D0);
                        uint32_t Ah2 = tmem + (t2 ? TM_A1H : TM_A0H);
                        uint32_t Al2 = tmem + (t2 ? TM_A1L : TM_A0L);
#pragma unroll
                        for (int s = 0; s < 8; s++)
                            TCGEN05_MMA_F16(D, Ah2 + s * 8, dh_next + OFFS[s], MMA_IDESC, s > 0);
#pragma unroll
                        for (int s = 0; s < 8; s++)
                            TCGEN05_MMA_F16(D, Al2 + s * 8, dh_next + OFFS[s], MMA_IDESC, true);
#pragma unroll
                        for (int s = 0; s < 8; s++)
                            TCGEN05_MMA_F16(D, Ah2 + s * 8, dl_next + OFFS[s], MMA_IDESC, true);
                        TCGEN05_COMMIT(mbar);
                    }
                }
            } else {
                float facc = 0.f;
#pragma unroll
                for (int j = 0; j < 32; j++) {
                    facc = fmaf(v0[j], s_W17[col0 + j], facc);
                    facc = fmaf(v1[j], s_W17[col0 + 32 + j], facc);
                }
                if (t2 == 0) acc0 = facc; else acc1 = facc;
            }
        }

        // both MMA(l) proven complete (both waits passed) -> buffer l&1 is free;
        // issue async bulk copy of layer l+2 weights into it
        if (l + 2 < NLAYERS && tid == 0) {
            const uint32_t wmb = (l & 1) ? wmbar1 : wmbar0;
            MBARRIER_EXPECT_TX(wmb, 65536);
            CP_BULK_G2S(sb + OFF_WBUF + (l & 1) * 65536, gW + (size_t)(l + 2) * 65536, 65536, wmb);
        }
    }

    // ---- fc17 finalize ----
    s_part[(0 * 128 + sub * 32 + lane) + half * 256] = acc0;
    s_part[(1 * 128 + sub * 32 + lane) + half * 256] = acc1;
    __syncthreads();
    out[blockIdx.x * 256 + tid] = s_part[tid] + s_part[tid + 256] + s_b17[0];

    __syncthreads();
    if (tid == 0) {
        MBARRIER_INVAL(mbar0); MBARRIER_INVAL(mbar1);
        MBARRIER_INVAL(wmbar0); MBARRIER_INVAL(wmbar1);
    }
    if (w == 0) {
        TCGEN05_RELINQUISH();
        TCGEN05_DEALLOC(tmem, 512);
    }
#else
    // ================= legacy HMMA implementation (compiles on base sm_103) =================
    extern __shared__ uint4 smem[];
    uint4* Wsm = smem;
    uint4* Hhi = smem + 4096;
    uint4* Hlo = smem + 8192;
    float* s_W1 = (float*)(smem + 12288);
    float* s_b1 = s_W1 + 256;
    float* s_bs = s_b1 + 128;
    float* s_W17 = s_bs + NLAYERS * 128;
    float* s_b17 = s_W17 + 128;

    const int tid = threadIdx.x;
    const int w = tid >> 5;
    const int lane = tid & 31;
    const int g = lane >> 2;
    const int c = lane & 3;

    s_W1[tid] = W1[tid];
    if (tid < 128) { s_b1[tid] = b1[tid]; s_W17[tid] = W17[tid]; }
    for (int i = tid; i < NLAYERS * 128; i += 256) s_bs[i] = bs[i];
    if (tid == 0) s_b17[0] = b17[0];
    __syncthreads();

    const int base_m = blockIdx.x * 256 + w * 32;

#pragma unroll
    for (int mt = 0; mt < 2; mt++) {
        int r0 = base_m + mt * 16 + g;
        float2 xa = *((const float2*)x + r0);
        float2 xb = *((const float2*)x + r0 + 8);
#pragma unroll
        for (int kt = 0; kt < 8; kt++) {
            float va[4], vb[4];
#pragma unroll
            for (int e = 0; e < 4; e++) {
                int j = kt * 16 + 2 * c + (e >> 1) * 8 + (e & 1);
                float w0 = s_W1[j], w1 = s_W1[128 + j], bb = s_b1[j];
                va[e] = fmaxf(fmaf(xa.y, w1, fmaf(xa.x, w0, bb)), 0.0f);
                vb[e] = fmaxf(fmaf(xb.y, w1, fmaf(xb.x, w0, bb)), 0.0f);
            }
            float ha[4], hb[4];
#pragma unroll
            for (int e = 0; e < 4; e++) { ha[e] = bf16_round(va[e]); hb[e] = bf16_round(vb[e]); }
            uint4 vh, vl;
            vh.x = pack2(ha[0], ha[1]); vh.y = pack2(hb[0], hb[1]);
            vh.z = pack2(ha[2], ha[3]); vh.w = pack2(hb[2], hb[3]);
            vl.x = pack2(va[0] - ha[0], va[1] - ha[1]);
            vl.y = pack2(vb[0] - hb[0], vb[1] - hb[1]);
            vl.z = pack2(va[2] - ha[2], va[3] - ha[3]);
            vl.w = pack2(vb[2] - hb[2], vb[3] - hb[3]);
            int hidx = ((w * 2 + mt) * 8 + kt) * 32 + lane;
            Hhi[hidx] = vh; Hlo[hidx] = vl;
        }
    }

    float C[2][16][4];

    for (int l = 0; l < NLAYERS; l++) {
        __syncthreads();
        {
            const uint4* Wp = g_W + l * 4096;
#pragma unroll
            for (int i = 0; i < 16; i++)
                Wsm[i * 256 + tid] = Wp[i * 256 + tid];
        }
        __syncthreads();

        const float* bias = s_bs + l * 128;
#pragma unroll
        for (int nt = 0; nt < 16; nt++) {
            float bb0 = bias[nt * 8 + 2 * c];
            float bb1 = bias[nt * 8 + 2 * c + 1];
#pragma unroll
            for (int mt = 0; mt < 2; mt++) {
                C[mt][nt][0] = bb0; C[mt][nt][1] = bb1;
                C[mt][nt][2] = bb0; C[mt][nt][3] = bb1;
            }
        }

#pragma unroll 2
        for (int kt = 0; kt < 8; kt++) {
            uint4 Ah[2], Al[2];
#pragma unroll
            for (int mt = 0; mt < 2; mt++) {
                int hidx = ((w * 2 + mt) * 8 + kt) * 32 + lane;
                Ah[mt] = Hhi[hidx]; Al[mt] = Hlo[hidx];
            }
#pragma unroll
            for (int nt = 0; nt < 16; nt++) {
                uint4 B = Wsm[(kt * 16 + nt) * 32 + lane];
#pragma unroll
                for (int mt = 0; mt < 2; mt++) {
                    mma_bf16(C[mt][nt], Ah[mt], B.x, B.y);
                    mma_bf16(C[mt][nt], Al[mt], B.x, B.y);
                    mma_bf16(C[mt][nt], Ah[mt], B.z, B.w);
                }
            }
        }

#pragma unroll
        for (int mt = 0; mt < 2; mt++)
#pragma unroll
            for (int nt = 0; nt < 16; nt++)
#pragma unroll
                for (int e = 0; e < 4; e++)
                    C[mt][nt][e] = fmaxf(C[mt][nt][e], 0.0f);

        if (l < NLAYERS - 1) {
#pragma unroll
            for (int mt = 0; mt < 2; mt++)
#pragma unroll
                for (int ktp = 0; ktp < 8; ktp++) {
                    const float* c0 = C[mt][2 * ktp];
                    const float* c1 = C[mt][2 * ktp + 1];
                    float h0 = bf16_round(c0[0]), h1 = bf16_round(c0[1]);
                    float h2 = bf16_round(c0[2]), h3 = bf16_round(c0[3]);
                    float h4 = bf16_round(c1[0]), h5 = bf16_round(c1[1]);
                    float h6 = bf16_round(c1[2]), h7 = bf16_round(c1[3]);
                    uint4 vh, vl;
                    vh.x = pack2(h0, h1); vh.y = pack2(h2, h3);
                    vh.z = pack2(h4, h5); vh.w = pack2(h6, h7);
                    vl.x = pack2(c0[0] - h0, c0[1] - h1);
                    vl.y = pack2(c0[2] - h2, c0[3] - h3);
                    vl.z = pack2(c1[0] - h4, c1[1] - h5);
                    vl.w = pack2(c1[2] - h6, c1[3] - h7);
                    int hidx = ((w * 2 + mt) * 8 + ktp) * 32 + lane;
                    Hhi[hidx] = vh; Hlo[hidx] = vl;
                }
        }
    }

    float acc[4] = {0.f, 0.f, 0.f, 0.f};
#pragma unroll
    for (int nt = 0; nt < 16; nt++) {
        float w0 = s_W17[nt * 8 + 2 * c];
        float w1 = s_W17[nt * 8 + 2 * c + 1];
#pragma unroll
        for (int mt = 0; mt < 2; mt++) {
            acc[mt * 2 + 0] = fmaf(C[mt][nt][0], w0, fmaf(C[mt][nt][1], w1, acc[mt * 2 + 0]));
            acc[mt * 2 + 1] = fmaf(C[mt][nt][2], w0, fmaf(C[mt][nt][3], w1, acc[mt * 2 + 1]));
        }
    }
#pragma unroll
    for (int i = 0; i < 4; i++) {
        acc[i] += __shfl_xor_sync(0xffffffffu, acc[i], 1);
        acc[i] += __shfl_xor_sync(0xffffffffu, acc[i], 2);
    }
    if (c == 0) {
        float bb = s_b17[0];
        out[base_m + g]          = acc[0] + bb;
        out[base_m + g + 8]      = acc[1] + bb;
        out[base_m + 16 + g]     = acc[2] + bb;
        out[base_m + 16 + g + 8] = acc[3] + bb;
    }
#endif
}

extern "C" void kernel_launch(void* const* d_in, const int* in_sizes, int n_in,
                              void* d_out, int out_size) {
    const float* x   = (const float*)d_in[0];
    const float* W1  = (const float*)d_in[1];
    const float* b1  = (const float*)d_in[2];
    const float* Ws  = (const float*)d_in[3];
    const float* bs  = (const float*)d_in[4];
    const float* W17 = (const float*)d_in[5];
    const float* b17 = (const float*)d_in[6];
    float* out = (float*)d_out;

    int nPoints = in_sizes[0] / 2;  // 1048576

    cudaFuncSetAttribute(mlp_kernel, cudaFuncAttributeMaxDynamicSharedMemorySize, SMEM_BYTES_MAX);

    prep_weights<<<480, 256>>>(Ws);
    mlp_kernel<<<nPoints / 256, 256, SMEM_BYTES_MAX>>>(x, W1, b1, bs, W17, b17, out);
}

// round 8
// speedup vs baseline: 1.3954x; 1.0651x over previous
#include <cuda_runtime.h>
#include <cuda_bf16.h>
#include <cstdint>

#define NLAYERS 15

// ---- arch-feature gate: tcgen05 only exists on sm_103a/'f' feature targets ----
#if defined(__CUDA_ARCH__)
#  if defined(__CUDA_ARCH_FEAT_SM103_ALL) || defined(__CUDA_ARCH_FEAT_SM100_ALL) || defined(__CUDA_ARCH_FAMILY_SPECIFIC__)
#    define USE_TC05 1
#  else
#    define USE_TC05 0
#  endif
#else
#  define USE_TC05 0
#endif

// ---------------- common helpers ----------------
static __device__ __forceinline__ uint32_t pack2(float e0, float e1) {
    uint32_t r;
    asm("cvt.rn.bf16x2.f32 %0, %1, %2;" : "=r"(r) : "f"(e1), "f"(e0));
    return r;
}
static __device__ __forceinline__ float bf16_round(float a) {
    return __bfloat162float(__float2bfloat16_rn(a));
}

// One global weight image; format depends on which branch compiled (both are 15*4096 uint4).
__device__ uint4 g_W[NLAYERS * 4096];

#if USE_TC05
__device__ __forceinline__ uint32_t elect_one_pred() {
    uint32_t pred;
    asm volatile("{\n\t.reg .pred p;\n\telect.sync _|p, 0xFFFFFFFF;\n\tselp.b32 %0, 1, 0, p;\n\t}"
                 : "=r"(pred));
    return pred;
}
#endif
__device__ __forceinline__ uint32_t smem_to_u32(const void* p) {
    uint32_t a;
    asm("{ .reg .u64 t; cvta.to.shared.u64 t, %1; cvt.u32.u64 %0, t; }" : "=r"(a) : "l"(p));
    return a;
}

#if USE_TC05
#define TCGEN05_ALLOC(smem_result_addr, nCols) \
    asm volatile("tcgen05.alloc.cta_group::1.sync.aligned.shared::cta.b32 [%0], %1;" \
                 :: "r"((uint32_t)(smem_result_addr)), "r"((uint32_t)(nCols)) : "memory")
#define TCGEN05_DEALLOC(tmem_addr, nCols) \
    asm volatile("tcgen05.dealloc.cta_group::1.sync.aligned.b32 %0, %1;" :: "r"(tmem_addr), "r"((uint32_t)(nCols)))
#define TCGEN05_RELINQUISH() \
    asm volatile("tcgen05.relinquish_alloc_permit.cta_group::1.sync.aligned;")
#define TCGEN05_WAIT_LD() asm volatile("tcgen05.wait::ld.sync.aligned;" ::: "memory")
#define TCGEN05_WAIT_ST() asm volatile("tcgen05.wait::st.sync.aligned;" ::: "memory")
#define TCGEN05_FENCE_BEFORE() asm volatile("tcgen05.fence::before_thread_sync;" ::: "memory")
#define TCGEN05_FENCE_AFTER()  asm volatile("tcgen05.fence::after_thread_sync;" ::: "memory")
#define TCGEN05_COMMIT(mbar) \
    asm volatile("tcgen05.commit.cta_group::1.mbarrier::arrive::one.shared::cluster.b64 [%0];" \
                 :: "r"((uint32_t)(mbar)) : "memory")
#define FENCE_PROXY_ASYNC() asm volatile("fence.proxy.async.shared::cta;" ::: "memory")
#define MBARRIER_INIT(mbar, cnt) \
    asm volatile("mbarrier.init.shared.b64 [%0], %1;" :: "r"((uint32_t)(mbar)), "r"((uint32_t)(cnt)) : "memory")
#define MBARRIER_INVAL(mbar) \
    asm volatile("mbarrier.inval.shared.b64 [%0];" :: "r"((uint32_t)(mbar)) : "memory")
#define MBARRIER_EXPECT_TX(mbar, bytes) \
    asm volatile("mbarrier.arrive.expect_tx.shared.b64 _, [%0], %1;" \
                 :: "r"((uint32_t)(mbar)), "r"((uint32_t)(bytes)) : "memory")
#define CP_BULK_G2S(dst_smem, src_gmem, nbytes, mbar) \
    asm volatile("cp.async.bulk.shared::cta.global.mbarrier::complete_tx::bytes [%0], [%1], %2, [%3];" \
                 :: "r"((uint32_t)(dst_smem)), "l"(src_gmem), "r"((uint32_t)(nbytes)), \
                    "r"((uint32_t)(mbar)) : "memory")
#define NAMED_BAR(id) asm volatile("bar.sync %0, 128;" :: "r"(id) : "memory")
#define MBARRIER_WAIT_PARITY(mbar, parity) do { \
    uint32_t _m = (uint32_t)(mbar); uint32_t _p = (uint32_t)(parity); uint32_t _d; \
    asm volatile("{\n\t.reg .pred p;\n\tmbarrier.try_wait.parity.acquire.cta.shared::cta.b64 p, [%1], %2;\n\tselp.b32 %0, 1, 0, p;\n\t}" \
                 : "=r"(_d) : "r"(_m), "r"(_p) : "memory"); \
    if (!_d) { \
        asm volatile("{\n\t.reg .pred P1;\n\tWL_%=: \n\tmbarrier.try_wait.parity.acquire.cta.shared::cta.b64 P1, [%0], %1, 0x989680;\n\t@P1 bra.uni WD_%=;\n\tbra.uni WL_%=;\n\tWD_%=: \n\t}" \
                     :: "r"(_m), "r"(_p) : "memory"); \
    } } while (0)

// TS form: A from TMEM
#define TCGEN05_MMA_F16(d_tmem, a_tmem, b_desc, idesc, enable_d) do { \
    uint32_t _en = (enable_d) ? 1u : 0u; uint32_t _z = 0u; \
    asm volatile("{\n\t.reg .pred p;\n\tsetp.ne.u32 p, %6, 0;\n\t" \
                 "tcgen05.mma.cta_group::1.kind::f16 [%0], [%1], %2, %3, {%4, %4, %4, %4}, p;\n\t}" \
                 :: "r"(d_tmem), "r"(a_tmem), "l"(b_desc), "r"(idesc), \
                    "r"(_z), "r"(_z), "r"(_en) : "memory"); \
} while (0)

#define TCGEN05_ST_X16(tmem_addr, r) \
    asm volatile("tcgen05.st.sync.aligned.32x32b.x16.b32 [%0], " \
                 "{%1,%2,%3,%4,%5,%6,%7,%8,%9,%10,%11,%12,%13,%14,%15,%16};" \
                 :: "r"(tmem_addr), \
                    "r"((r)[0]), "r"((r)[1]), "r"((r)[2]), "r"((r)[3]), \
                    "r"((r)[4]), "r"((r)[5]), "r"((r)[6]), "r"((r)[7]), \
                    "r"((r)[8]), "r"((r)[9]), "r"((r)[10]), "r"((r)[11]), \
                    "r"((r)[12]), "r"((r)[13]), "r"((r)[14]), "r"((r)[15]) : "memory")

#define TCGEN05_LD_X32(r, tmem_addr) \
    asm volatile("tcgen05.ld.sync.aligned.32x32b.x32.b32 " \
                 "{%0,%1,%2,%3,%4,%5,%6,%7,%8,%9,%10,%11,%12,%13,%14,%15," \
                 "%16,%17,%18,%19,%20,%21,%22,%23,%24,%25,%26,%27,%28,%29,%30,%31}, [%32];" \
                 : "=r"((r)[0]), "=r"((r)[1]), "=r"((r)[2]), "=r"((r)[3]), \
                   "=r"((r)[4]), "=r"((r)[5]), "=r"((r)[6]), "=r"((r)[7]), \
                   "=r"((r)[8]), "=r"((r)[9]), "=r"((r)[10]), "=r"((r)[11]), \
                   "=r"((r)[12]), "=r"((r)[13]), "=r"((r)[14]), "=r"((r)[15]), \
                   "=r"((r)[16]), "=r"((r)[17]), "=r"((r)[18]), "=r"((r)[19]), \
                   "=r"((r)[20]), "=r"((r)[21]), "=r"((r)[22]), "=r"((r)[23]), \
                   "=r"((r)[24]), "=r"((r)[25]), "=r"((r)[26]), "=r"((r)[27]), \
                   "=r"((r)[28]), "=r"((r)[29]), "=r"((r)[30]), "=r"((r)[31]) \
                 : "r"(tmem_addr))

static constexpr uint64_t SMEM_DESC_BASE_SW128 =
    (uint64_t(2) << 61) | (uint64_t(1) << 46) | (uint64_t(64) << 32) | (uint64_t(1) << 16);
#define MAKE_SMEM_DESC(base_addr) (SMEM_DESC_BASE_SW128 | ((uint64_t)((base_addr) >> 4) & 0x3FFF))
// idesc kind::f16: dtype=F32, atype=btype=BF16, N=128, M=128
#define MMA_IDESC 0x8200490u
#else
static __device__ __forceinline__ void mma_bf16(float C[4], uint4 A, uint32_t b0, uint32_t b1) {
    asm("mma.sync.aligned.m16n8k16.row.col.f32.bf16.bf16.f32 "
        "{%0,%1,%2,%3}, {%4,%5,%6,%7}, {%8,%9}, {%0,%1,%2,%3};"
        : "+f"(C[0]), "+f"(C[1]), "+f"(C[2]), "+f"(C[3])
        : "r"(A.x), "r"(A.y), "r"(A.z), "r"(A.w), "r"(b0), "r"(b1));
}
#endif

// ---------------- weight pre-pack (format matches the arch branch) ----------------
__global__ void prep_weights(const float* __restrict__ Ws) {
    int t = blockIdx.x * blockDim.x + threadIdx.x;
#if USE_TC05
    if (t >= NLAYERS * 128 * 64) return;
    int kp = t & 63;          // k pair index
    int n = (t >> 6) & 127;   // N row
    int l = t >> 13;
    int k = kp * 2;
    const float* W = Ws + l * 16384;
    float w0 = W[k * 128 + n], w1 = W[(k + 1) * 128 + n];
    float h0 = bf16_round(w0), h1 = bf16_round(w1);
    uint32_t hi = pack2(h0, h1);
    uint32_t lo = pack2(w0 - h0, w1 - h1);
    int atom_row = n >> 3, inner_row = n & 7, atom_col = k >> 6, inner_col = k & 63;
    uint32_t byte = (uint32_t)(atom_row + atom_col * 16) * 1024u + inner_row * 128u + inner_col * 2u;
    uint32_t sw = byte ^ ((byte >> 3) & 0x70);
    char* base = (char*)g_W + (size_t)l * 65536;
    *(uint32_t*)(base + sw) = hi;
    *(uint32_t*)(base + 32768 + sw) = lo;
#else
    if (t >= NLAYERS * 4096) return;
    int lane = t & 31;
    int nt = (t >> 5) & 15;
    int kt = (t >> 9) & 7;
    int l = t >> 12;
    int c = lane & 3, g = lane >> 2;
    int n = nt * 8 + g;
    const float* W = Ws + l * 128 * 128;
    int k0 = kt * 16 + 2 * c;
    float w00 = W[(k0 + 0) * 128 + n];
    float w01 = W[(k0 + 1) * 128 + n];
    float w10 = W[(k0 + 8) * 128 + n];
    float w11 = W[(k0 + 9) * 128 + n];
    float h00 = bf16_round(w00), h01 = bf16_round(w01);
    float h10 = bf16_round(w10), h11 = bf16_round(w11);
    uint4 v;
    v.x = pack2(h00, h01);
    v.y = pack2(h10, h11);
    v.z = pack2(w00 - h00, w01 - h01);
    v.w = pack2(w10 - h10, w11 - h11);
    g_W[t] = v;
#endif
}

// ---------------- tcgen05 smem layout ----------------
#define OFF_WBUF   0        // 2 x 65536 (Whi 32KB + Wlo 32KB per buffer)
#define OFF_BS     131072   // 1920 f
#define OFF_W1     138752   // 256 f
#define OFF_B1     139776   // 128 f
#define OFF_W17    140288   // 128 f
#define OFF_B17    140800   // 16
#define OFF_MBAR   140816   // 2 x u64 (MMA commit barriers)
#define OFF_WMBAR  140832   // 2 x u64 (weight copy barriers)
#define OFF_TPTR   140848
#define SMEM_TC05  140864
// legacy path needs 206352; take max
#define SMEM_BYTES_MAX 206352

// TMEM column map (512 cols)
#define TM_D0   0
#define TM_D1   128
#define TM_A0H  256
#define TM_A0L  320
#define TM_A1H  384
#define TM_A1L  448

__global__ void __launch_bounds__(256, 1)
mlp_kernel(const float* __restrict__ x,
           const float* __restrict__ W1,
           const float* __restrict__ b1,
           const float* __restrict__ bs,
           const float* __restrict__ W17,
           const float* __restrict__ b17,
           float* __restrict__ out) {
#if USE_TC05
    // ===== tcgen05 TS, tile-parallel epilogues, TMA bulk weight prefetch =====
    extern __shared__ char smem[];
    float* s_bs = (float*)(smem + OFF_BS);
    float* s_W1 = (float*)(smem + OFF_W1);
    float* s_b1 = (float*)(smem + OFF_B1);
    float* s_W17 = (float*)(smem + OFF_W17);
    float* s_b17 = (float*)(smem + OFF_B17);

    const uint32_t sb = smem_to_u32(smem);
    const uint32_t wmbar0 = sb + OFF_WMBAR;
    const uint32_t wmbar1 = sb + OFF_WMBAR + 8;

    const int tid = threadIdx.x;
    const int w = tid >> 5;
    const int lane = tid & 31;
    const int sub = w & 3;       // TMEM subpartition (= warpid % 4)
    const int grp = w >> 2;      // tile group: warps 0-3 tile0, warps 4-7 tile1
    const uint32_t toff = (uint32_t)sub << 21;
    const int p = sub * 32 + lane;   // point row within tile

    const uint32_t mbar_g = sb + OFF_MBAR + grp * 8;
    const uint32_t tmD  = grp ? TM_D1 : TM_D0;
    const uint32_t tmAH = grp ? TM_A1H : TM_A0H;
    const uint32_t tmAL = grp ? TM_A1L : TM_A0L;
    const bool leader = (sub == 0);

    const char* gW = (const char*)g_W;

    for (int i = tid; i < NLAYERS * 128; i += 256) s_bs[i] = bs[i];
    s_W1[tid] = W1[tid];
    if (tid < 128) { s_b1[tid] = b1[tid]; s_W17[tid] = W17[tid]; }
    if (tid == 0) {
        s_b17[0] = b17[0];
        MBARRIER_INIT(sb + OFF_MBAR, 1);
        MBARRIER_INIT(sb + OFF_MBAR + 8, 1);
        MBARRIER_INIT(wmbar0, 1);
        MBARRIER_INIT(wmbar1, 1);
    }
    // stage layer-0 weights via LDG (one-time; proxy fence below covers it)
    {
        const uint4* src = g_W;
        uint4* dst = (uint4*)smem;
#pragma unroll
        for (int i = 0; i < 16; i++)
            dst[i * 256 + tid] = src[i * 256 + tid];
    }
    if (w == 0) TCGEN05_ALLOC(sb + OFF_TPTR, 512);
    FENCE_PROXY_ASYNC();
    __syncthreads();
    uint32_t tmem;
    asm volatile("ld.shared.b32 %0, [%1];" : "=r"(tmem) : "r"(sb + OFF_TPTR));

    // kick off layer-1 weight bulk copy (async, completes on wmbar1 phase 0)
    if (tid == 0) {
        MBARRIER_EXPECT_TX(wmbar1, 65536);
        CP_BULK_G2S(sb + OFF_WBUF + 65536, gW + 65536, 65536, wmbar1);
    }

    const uint32_t aH = tmem + tmAH + toff;
    const uint32_t aL = tmem + tmAL + toff;
    const uint32_t Dbase = tmem + tmD + toff;

    // ---- fc1: relu(x@W1+b1) -> A tile (grp) in TMEM (hi/lo bf16x2) ----
    {
        const int row = blockIdx.x * 256 + grp * 128 + p;
        const float2 xv = ((const float2*)x)[row];
#pragma unroll
        for (int cc = 0; cc < 4; cc++) {
            uint32_t rh[16], rl[16];
#pragma unroll
            for (int j = 0; j < 16; j++) {
                int n0 = cc * 32 + 2 * j;
                float v0 = fmaxf(fmaf(xv.y, s_W1[128 + n0], fmaf(xv.x, s_W1[n0], s_b1[n0])), 0.f);
                float v1 = fmaxf(fmaf(xv.y, s_W1[128 + n0 + 1], fmaf(xv.x, s_W1[n0 + 1], s_b1[n0 + 1])), 0.f);
                uint32_t hi = pack2(v0, v1);
                float h0 = __uint_as_float(hi << 16);
                float h1 = __uint_as_float(hi & 0xFFFF0000u);
                rh[j] = hi;
                rl[j] = pack2(v0 - h0, v1 - h1);
            }
            TCGEN05_ST_X16(aH + cc * 16, rh);
            TCGEN05_ST_X16(aL + cc * 16, rl);
        }
        TCGEN05_WAIT_ST();
    }
    TCGEN05_FENCE_BEFORE();
    __syncthreads();

    const uint32_t OFFS[8] = {0, 2, 4, 6, 1024, 1026, 1028, 1030};

    // ---- issue layer 0 MMA for this group's tile (warps 0 and 4) ----
    if (leader) {
        TCGEN05_FENCE_AFTER();
        if (elect_one_pred()) {
            uint64_t dh = MAKE_SMEM_DESC(sb + OFF_WBUF);
            uint64_t dl = dh + 2048;
            uint32_t D = tmem + tmD;
            uint32_t Ah = tmem + tmAH;
            uint32_t Al = tmem + tmAL;
#pragma unroll
            for (int s = 0; s < 8; s++)
                TCGEN05_MMA_F16(D, Ah + s * 8, dh + OFFS[s], MMA_IDESC, s > 0);
#pragma unroll
            for (int s = 0; s < 8; s++)
                TCGEN05_MMA_F16(D, Al + s * 8, dh + OFFS[s], MMA_IDESC, true);
#pragma unroll
            for (int s = 0; s < 8; s++)
                TCGEN05_MMA_F16(D, Ah + s * 8, dl + OFFS[s], MMA_IDESC, true);
            TCGEN05_COMMIT(mbar_g);
        }
    }

    int wph0 = 0, wph1 = 0;   // weight-copy mbar phases (leader warps)

    // ---- fc2..fc16, tile-parallel epilogues ----
    for (int l = 0; l < NLAYERS; l++) {
        const uint32_t ph = (uint32_t)(l & 1);
        const bool last = (l == NLAYERS - 1);
        const float* bias = s_bs + l * 128;
        const uint64_t dh_next = MAKE_SMEM_DESC(sb + OFF_WBUF + ((l + 1) & 1) * 65536);
        const uint64_t dl_next = dh_next + 2048;

        MBARRIER_WAIT_PARITY(mbar_g, ph);
        TCGEN05_FENCE_AFTER();

        float facc = 0.f;
#pragma unroll
        for (int c = 0; c < 2; c++) {
            uint32_t vr0[32], vr1[32];
            TCGEN05_LD_X32(vr0, Dbase + c * 64);
            TCGEN05_LD_X32(vr1, Dbase + c * 64 + 32);
            TCGEN05_WAIT_LD();
            float v0[32], v1[32];
#pragma unroll
            for (int j = 0; j < 32; j++) {
                v0[j] = fmaxf(__uint_as_float(vr0[j]) + bias[c * 64 + j], 0.f);
                v1[j] = fmaxf(__uint_as_float(vr1[j]) + bias[c * 64 + 32 + j], 0.f);
            }
            if (!last) {
                uint32_t rh0[16], rl0[16], rh1[16], rl1[16];
#pragma unroll
                for (int j = 0; j < 16; j++) {
                    uint32_t hi0 = pack2(v0[2 * j], v0[2 * j + 1]);
                    rh0[j] = hi0;
                    rl0[j] = pack2(v0[2 * j] - __uint_as_float(hi0 << 16),
                                   v0[2 * j + 1] - __uint_as_float(hi0 & 0xFFFF0000u));
                    uint32_t hi1 = pack2(v1[2 * j], v1[2 * j + 1]);
                    rh1[j] = hi1;
                    rl1[j] = pack2(v1[2 * j] - __uint_as_float(hi1 << 16),
                                   v1[2 * j + 1] - __uint_as_float(hi1 & 0xFFFF0000u));
                }
                TCGEN05_ST_X16(aH + c * 32, rh0);
                TCGEN05_ST_X16(aH + c * 32 + 16, rh1);
                TCGEN05_ST_X16(aL + c * 32, rl0);
                TCGEN05_ST_X16(aL + c * 32 + 16, rl1);
            } else {
#pragma unroll
                for (int j = 0; j < 32; j++) {
                    facc = fmaf(v0[j], s_W17[c * 64 + j], facc);
                    facc = fmaf(v1[j], s_W17[c * 64 + 32 + j], facc);
                }
            }
        }

        if (!last) {
            TCGEN05_WAIT_ST();
            TCGEN05_FENCE_BEFORE();
            NAMED_BAR(grp + 1);   // this group's A tile fully written
            if (leader) {
                // ensure next layer's weight buffer has arrived
                if ((l + 1) & 1) { MBARRIER_WAIT_PARITY(wmbar1, wph1); wph1 ^= 1; }
                else             { MBARRIER_WAIT_PARITY(wmbar0, wph0); wph0 ^= 1; }
                TCGEN05_FENCE_AFTER();
                if (elect_one_pred()) {
                    uint32_t D = tmem + tmD;
                    uint32_t Ah2 = tmem + tmAH;
                    uint32_t Al2 = tmem + tmAL;
#pragma unroll
                    for (int s = 0; s < 8; s++)
                        TCGEN05_MMA_F16(D, Ah2 + s * 8, dh_next + OFFS[s], MMA_IDESC, s > 0);
#pragma unroll
                    for (int s = 0; s < 8; s++)
                        TCGEN05_MMA_F16(D, Al2 + s * 8, dh_next + OFFS[s], MMA_IDESC, true);
#pragma unroll
                    for (int s = 0; s < 8; s++)
                        TCGEN05_MMA_F16(D, Ah2 + s * 8, dl_next + OFFS[s], MMA_IDESC, true);
                    TCGEN05_COMMIT(mbar_g);
                }
            }
            __syncthreads();   // both groups passed their mbar waits -> buffer l&1 free
            if (l + 2 < NLAYERS && tid == 0) {
                const uint32_t wmb = (l & 1) ? wmbar1 : wmbar0;
                MBARRIER_EXPECT_TX(wmb, 65536);
                CP_BULK_G2S(sb + OFF_WBUF + (l & 1) * 65536, gW + (size_t)(l + 2) * 65536, 65536, wmb);
            }
        } else {
            out[blockIdx.x * 256 + grp * 128 + p] = facc + s_b17[0];
        }
    }

    __syncthreads();
    if (tid == 0) {
        MBARRIER_INVAL(sb + OFF_MBAR); MBARRIER_INVAL(sb + OFF_MBAR + 8);
        MBARRIER_INVAL(wmbar0); MBARRIER_INVAL(wmbar1);
    }
    if (w == 0) {
        TCGEN05_RELINQUISH();
        TCGEN05_DEALLOC(tmem, 512);
    }
#else
    // ================= legacy HMMA implementation (compiles on base sm_103) =================
    extern __shared__ uint4 smem[];
    uint4* Wsm = smem;
    uint4* Hhi = smem + 4096;
    uint4* Hlo = smem + 8192;
    float* s_W1 = (float*)(smem + 12288);
    float* s_b1 = s_W1 + 256;
    float* s_bs = s_b1 + 128;
    float* s_W17 = s_bs + NLAYERS * 128;
    float* s_b17 = s_W17 + 128;

    const int tid = threadIdx.x;
    const int w = tid >> 5;
    const int lane = tid & 31;
    const int g = lane >> 2;
    const int c = lane & 3;

    s_W1[tid] = W1[tid];
    if (tid < 128) { s_b1[tid] = b1[tid]; s_W17[tid] = W17[tid]; }
    for (int i = tid; i < NLAYERS * 128; i += 256) s_bs[i] = bs[i];
    if (tid == 0) s_b17[0] = b17[0];
    __syncthreads();

    const int base_m = blockIdx.x * 256 + w * 32;

#pragma unroll
    for (int mt = 0; mt < 2; mt++) {
        int r0 = base_m + mt * 16 + g;
        float2 xa = *((const float2*)x + r0);
        float2 xb = *((const float2*)x + r0 + 8);
#pragma unroll
        for (int kt = 0; kt < 8; kt++) {
            float va[4], vb[4];
#pragma unroll
            for (int e = 0; e < 4; e++) {
                int j = kt * 16 + 2 * c + (e >> 1) * 8 + (e & 1);
                float w0 = s_W1[j], w1 = s_W1[128 + j], bb = s_b1[j];
                va[e] = fmaxf(fmaf(xa.y, w1, fmaf(xa.x, w0, bb)), 0.0f);
                vb[e] = fmaxf(fmaf(xb.y, w1, fmaf(xb.x, w0, bb)), 0.0f);
            }
            float ha[4], hb[4];
#pragma unroll
            for (int e = 0; e < 4; e++) { ha[e] = bf16_round(va[e]); hb[e] = bf16_round(vb[e]); }
            uint4 vh, vl;
            vh.x = pack2(ha[0], ha[1]); vh.y = pack2(hb[0], hb[1]);
            vh.z = pack2(ha[2], ha[3]); vh.w = pack2(hb[2], hb[3]);
            vl.x = pack2(va[0] - ha[0], va[1] - ha[1]);
            vl.y = pack2(vb[0] - hb[0], vb[1] - hb[1]);
            vl.z = pack2(va[2] - ha[2], va[3] - ha[3]);
            vl.w = pack2(vb[2] - hb[2], vb[3] - hb[3]);
            int hidx = ((w * 2 + mt) * 8 + kt) * 32 + lane;
            Hhi[hidx] = vh; Hlo[hidx] = vl;
        }
    }

    float C[2][16][4];

    for (int l = 0; l < NLAYERS; l++) {
        __syncthreads();
        {
            const uint4* Wp = g_W + l * 4096;
#pragma unroll
            for (int i = 0; i < 16; i++)
                Wsm[i * 256 + tid] = Wp[i * 256 + tid];
        }
        __syncthreads();

        const float* bias = s_bs + l * 128;
#pragma unroll
        for (int nt = 0; nt < 16; nt++) {
            float bb0 = bias[nt * 8 + 2 * c];
            float bb1 = bias[nt * 8 + 2 * c + 1];
#pragma unroll
            for (int mt = 0; mt < 2; mt++) {
                C[mt][nt][0] = bb0; C[mt][nt][1] = bb1;
                C[mt][nt][2] = bb0; C[mt][nt][3] = bb1;
            }
        }

#pragma unroll 2
        for (int kt = 0; kt < 8; kt++) {
            uint4 Ah[2], Al[2];
#pragma unroll
            for (int mt = 0; mt < 2; mt++) {
                int hidx = ((w * 2 + mt) * 8 + kt) * 32 + lane;
                Ah[mt] = Hhi[hidx]; Al[mt] = Hlo[hidx];
            }
#pragma unroll
            for (int nt = 0; nt < 16; nt++) {
                uint4 B = Wsm[(kt * 16 + nt) * 32 + lane];
#pragma unroll
                for (int mt = 0; mt < 2; mt++) {
                    mma_bf16(C[mt][nt], Ah[mt], B.x, B.y);
                    mma_bf16(C[mt][nt], Al[mt], B.x, B.y);
                    mma_bf16(C[mt][nt], Ah[mt], B.z, B.w);
                }
            }
        }

#pragma unroll
        for (int mt = 0; mt < 2; mt++)
#pragma unroll
            for (int nt = 0; nt < 16; nt++)
#pragma unroll
                for (int e = 0; e < 4; e++)
                    C[mt][nt][e] = fmaxf(C[mt][nt][e], 0.0f);

        if (l < NLAYERS - 1) {
#pragma unroll
            for (int mt = 0; mt < 2; mt++)
#pragma unroll
                for (int ktp = 0; ktp < 8; ktp++) {
                    const float* c0 = C[mt][2 * ktp];
                    const float* c1 = C[mt][2 * ktp + 1];
                    float h0 = bf16_round(c0[0]), h1 = bf16_round(c0[1]);
                    float h2 = bf16_round(c0[2]), h3 = bf16_round(c0[3]);
                    float h4 = bf16_round(c1[0]), h5 = bf16_round(c1[1]);
                    float h6 = bf16_round(c1[2]), h7 = bf16_round(c1[3]);
                    uint4 vh, vl;
                    vh.x = pack2(h0, h1); vh.y = pack2(h2, h3);
                    vh.z = pack2(h4, h5); vh.w = pack2(h6, h7);
                    vl.x = pack2(c0[0] - h0, c0[1] - h1);
                    vl.y = pack2(c0[2] - h2, c0[3] - h3);
                    vl.z = pack2(c1[0] - h4, c1[1] - h5);
                    vl.w = pack2(c1[2] - h6, c1[3] - h7);
                    int hidx = ((w * 2 + mt) * 8 + ktp) * 32 + lane;
                    Hhi[hidx] = vh; Hlo[hidx] = vl;
                }
        }
    }

    float acc[4] = {0.f, 0.f, 0.f, 0.f};
#pragma unroll
    for (int nt = 0; nt < 16; nt++) {
        float w0 = s_W17[nt * 8 + 2 * c];
        float w1 = s_W17[nt * 8 + 2 * c + 1];
#pragma unroll
        for (int mt = 0; mt < 2; mt++) {
            acc[mt * 2 + 0] = fmaf(C[mt][nt][0], w0, fmaf(C[mt][nt][1], w1, acc[mt * 2 + 0]));
            acc[mt * 2 + 1] = fmaf(C[mt][nt][2], w0, fmaf(C[mt][nt][3], w1, acc[mt * 2 + 1]));
        }
    }
#pragma unroll
    for (int i = 0; i < 4; i++) {
        acc[i] += __shfl_xor_sync(0xffffffffu, acc[i], 1);
        acc[i] += __shfl_xor_sync(0xffffffffu, acc[i], 2);
    }
    if (c == 0) {
        float bb = s_b17[0];
        out[base_m + g]          = acc[0] + bb;
        out[base_m + g + 8]      = acc[1] + bb;
        out[base_m + 16 + g]     = acc[2] + bb;
        out[base_m + 16 + g + 8] = acc[3] + bb;
    }
#endif
}

extern "C" void kernel_launch(void* const* d_in, const int* in_sizes, int n_in,
                              void* d_out, int out_size) {
    const float* x   = (const float*)d_in[0];
    const float* W1  = (const float*)d_in[1];
    const float* b1  = (const float*)d_in[2];
    const float* Ws  = (const float*)d_in[3];
    const float* bs  = (const float*)d_in[4];
    const float* W17 = (const float*)d_in[5];
    const float* b17 = (const float*)d_in[6];
    float* out = (float*)d_out;

    int nPoints = in_sizes[0] / 2;  // 1048576

    cudaFuncSetAttribute(mlp_kernel, cudaFuncAttributeMaxDynamicSharedMemorySize, SMEM_BYTES_MAX);

    prep_weights<<<480, 256>>>(Ws);
    mlp_kernel<<<nPoints / 256, 256, SMEM_BYTES_MAX>>>(x, W1, b1, bs, W17, b17, out);
}